// round 12
// baseline (speedup 1.0000x reference)
#include <cuda_runtime.h>
#include <cuda_fp16.h>
#include <cstdint>

#define SEQ    512
#define BATCH  64
#define DIM    512
#define MAXLEN 512
#define NWORDS (SEQ/32)

#define UTILE   64            // u rows per CTA
#define KCHUNK  64            // fp32 k elems per chunk -> 128B fp16 row
#define NCHUNKS (DIM/KCHUNK)  // 8
#define KSTEPS  4             // four k=16 MMA steps per chunk

// ---- stage layout (bytes) ----
#define SM_A      0                       // 64 rows x 128B = 8 KB
#define SM_B      8192                    // 512 rows x 128B = 64 KB
#define STAGE_BYTES 73728
#define NSTAGES   3
#define SM_TOTAL  (NSTAGES*STAGE_BYTES)   // 221184

#define PREP_T   256
#define MMA_T    512          // 16 warps: 2(u) x 8(s)

#define CONVM_ITEMS (BATCH * NCHUNKS * SEQ * 8)   // 262144
#define CONVW_ITEMS (NCHUNKS * MAXLEN * 8)        // 32768

// ---- persistent device scratch ----
__device__ uint4 gMc[BATCH * NCHUNKS * SEQ * 8];   // 32 MB
__device__ uint4 gWc[NCHUNKS * MAXLEN * 8];        // 512 KB
// Zero at module load; mea_mma's epilogue re-zeroes every word it consumes,
// so every invocation (correctness run + each graph replay) leaves it zeroed.
__device__ unsigned g_maskbits[BATCH * MAXLEN * NWORDS];

// One kernel: mask-build + conv_M + conv_W, block-range partitioned.
__global__ void prep_kernel(const int* __restrict__ eb,
                            const int* __restrict__ eu,
                            const int* __restrict__ ev, int E, int edgeBlocks,
                            const float* __restrict__ Mm,
                            const float* __restrict__ Wm) {
    const int bid = blockIdx.x;
    const int tid = threadIdx.x;

    if (bid < edgeBlocks) {                     // ---- build mask ----
        int i = bid * PREP_T + tid;
        if (i < E)
            atomicOr(&g_maskbits[(eb[i] * MAXLEN + eu[i]) * NWORDS + (ev[i] >> 5)],
                     1u << (ev[i] & 31));
        return;
    }
    int b2 = bid - edgeBlocks;
    if (b2 < CONVM_ITEMS / PREP_T) {            // ---- conv M -> fp16 rows ----
        int i = b2 * PREP_T + tid;
        int f8 = i & 7, s = (i >> 3) & 511, ck = (i >> 12) & 7, b = i >> 15;
        const float* src = &Mm[((size_t)s * BATCH + b) * DIM + ck * KCHUNK + f8 * 8];
        float4 v0 = *(const float4*)src;
        float4 v1 = *(const float4*)(src + 4);
        __half2 h0 = __floats2half2_rn(v0.x, v0.y);
        __half2 h1 = __floats2half2_rn(v0.z, v0.w);
        __half2 h2 = __floats2half2_rn(v1.x, v1.y);
        __half2 h3 = __floats2half2_rn(v1.z, v1.w);
        uint4 o; o.x = *(uint32_t*)&h0; o.y = *(uint32_t*)&h1;
                 o.z = *(uint32_t*)&h2; o.w = *(uint32_t*)&h3;
        *(uint4*)((char*)gMc + ((size_t)((b * NCHUNKS + ck) * SEQ + s)) * 128 + f8 * 16) = o;
        return;
    }
    int b3 = b2 - CONVM_ITEMS / PREP_T;         // ---- conv W -> fp16 rows ----
    {
        int i = b3 * PREP_T + tid;
        if (i >= CONVW_ITEMS) return;
        int f8 = i & 7, u = (i >> 3) & 511, ck = i >> 12;
        const float* src = &Wm[(size_t)u * DIM + ck * KCHUNK + f8 * 8];
        float4 v0 = *(const float4*)src;
        float4 v1 = *(const float4*)(src + 4);
        __half2 h0 = __floats2half2_rn(v0.x, v0.y);
        __half2 h1 = __floats2half2_rn(v0.z, v0.w);
        __half2 h2 = __floats2half2_rn(v1.x, v1.y);
        __half2 h3 = __floats2half2_rn(v1.z, v1.w);
        uint4 o; o.x = *(uint32_t*)&h0; o.y = *(uint32_t*)&h1;
                 o.z = *(uint32_t*)&h2; o.w = *(uint32_t*)&h3;
        *(uint4*)((char*)gWc + ((size_t)(ck * MAXLEN + u)) * 128 + f8 * 16) = o;
    }
}

// ---------------- helpers ----------------
__device__ __forceinline__ uint32_t smem_u32(const void* p) {
    uint32_t a;
    asm("{ .reg .u64 t; cvta.to.shared.u64 t, %1; cvt.u32.u64 %0, t; }" : "=r"(a) : "l"(p));
    return a;
}
__device__ __forceinline__ uint32_t sw128(uint32_t off) { return off ^ ((off >> 3) & 0x70); }

__device__ __forceinline__ void ldsm_x4(uint32_t& r0, uint32_t& r1,
                                        uint32_t& r2, uint32_t& r3, uint32_t addr) {
    asm volatile("ldmatrix.sync.aligned.m8n8.x4.shared.b16 {%0,%1,%2,%3}, [%4];"
                 : "=r"(r0), "=r"(r1), "=r"(r2), "=r"(r3) : "r"(addr));
}

__device__ __forceinline__ void mma16816(float* d, const uint32_t* a,
                                         uint32_t b0, uint32_t b1) {
    asm volatile("mma.sync.aligned.m16n8k16.row.col.f32.f16.f16.f32 "
                 "{%0,%1,%2,%3}, {%4,%5,%6,%7}, {%8,%9}, {%0,%1,%2,%3};"
                 : "+f"(d[0]), "+f"(d[1]), "+f"(d[2]), "+f"(d[3])
                 : "r"(a[0]), "r"(a[1]), "r"(a[2]), "r"(a[3]), "r"(b0), "r"(b1));
}

__device__ __forceinline__ void cp16(uint32_t dst, const void* src) {
    asm volatile("cp.async.cg.shared.global [%0], [%1], 16;" :: "r"(dst), "l"(src));
}

__device__ __forceinline__ void load_stage(uint32_t sb, int stage, int ck,
                                           int b, int utile, int tid) {
    const uint32_t sbase = sb + stage * STAGE_BYTES;
    const char* srcB = (const char*)gMc + ((size_t)((b * NCHUNKS + ck) * SEQ)) * 128;
    #pragma unroll
    for (int it = 0; it < 8; it++) {
        int idx = it * MMA_T + tid;
        int s = idx >> 3, f4 = idx & 7;
        cp16(sbase + SM_B + sw128((uint32_t)(s * 128 + f4 * 16)),
             srcB + s * 128 + f4 * 16);
    }
    {
        int u = tid >> 3, f4 = tid & 7;
        cp16(sbase + SM_A + sw128((uint32_t)(u * 128 + f4 * 16)),
             (const char*)gWc + ((size_t)(ck * MAXLEN + utile + u)) * 128 + f4 * 16);
    }
    asm volatile("cp.async.commit_group;");
}

__global__ __launch_bounds__(MMA_T, 1)
void mea_mma_kernel(float* __restrict__ out) {    // (BATCH, MAXLEN, SEQ)
    extern __shared__ char smem[];
    const uint32_t sb = smem_u32(smem);
    const int tid  = threadIdx.x;
    const int wid  = tid >> 5;
    const int lane = tid & 31;
    const int wu   = wid >> 3;      // 0..1 : u-slice (32 rows)
    const int ws   = wid & 7;       // 0..7 : s-slice (64 cols)
    const int b     = blockIdx.y;
    const int utile = blockIdx.x * UTILE;

    // ldmatrix per-lane address components (SW128, 128B rows)
    const int xr     = (lane & 7) << 4;
    const int a_kh   = (lane >> 4) * 16;
    const int b_rowl = ((lane >> 4) << 3) + (lane & 7);
    const int b_kh   = ((lane >> 3) & 1) << 4;
    const uint32_t aRow0 = (uint32_t)((wu * 32 + (lane & 15)) * 128);
    const uint32_t aRow1 = aRow0 + 16 * 128;
    const uint32_t bRow  = (uint32_t)(SM_B + (ws * 64 + b_rowl) * 128);

    float acc0[8][4], acc1[8][4];   // row-groups (u+0..15) and (u+16..31), 64 s-cols
    #pragma unroll
    for (int nt = 0; nt < 8; nt++)
        #pragma unroll
        for (int j = 0; j < 4; j++) { acc0[nt][j] = 0.f; acc1[nt][j] = 0.f; }

    load_stage(sb, 0, 0, b, utile, tid);
    load_stage(sb, 1, 1, b, utile, tid);

    #pragma unroll 1
    for (int ck = 0; ck < NCHUNKS; ck++) {
        if (ck == NCHUNKS - 1) asm volatile("cp.async.wait_group 0;" ::: "memory");
        else                   asm volatile("cp.async.wait_group 1;" ::: "memory");
        __syncthreads();
        if (ck + 2 < NCHUNKS)
            load_stage(sb, (ck + 2) % NSTAGES, ck + 2, b, utile, tid);

        const uint32_t sbase = sb + (ck % NSTAGES) * STAGE_BYTES;
        const uint32_t aB0 = sbase + SM_A + aRow0;
        const uint32_t aB1 = sbase + SM_A + aRow1;
        const uint32_t bB  = sbase + bRow;

        #pragma unroll
        for (int ks = 0; ks < KSTEPS; ks++) {
            const uint32_t ac = (uint32_t)((ks * 32 + a_kh) ^ xr);
            const uint32_t bc = (uint32_t)((ks * 32 + b_kh) ^ xr);
            uint32_t a0[4], a1[4];
            ldsm_x4(a0[0], a0[1], a0[2], a0[3], aB0 + ac);
            ldsm_x4(a1[0], a1[1], a1[2], a1[3], aB1 + ac);
            #pragma unroll
            for (int np = 0; np < 4; np++) {
                uint32_t b0, b1, b2, b3;
                ldsm_x4(b0, b1, b2, b3, bB + np * 2048 + bc);
                mma16816(acc0[2*np+0], a0, b0, b1);
                mma16816(acc0[2*np+1], a0, b2, b3);
                mma16816(acc1[2*np+0], a1, b0, b1);
                mma16816(acc1[2*np+1], a1, b2, b3);
            }
        }
    }
    __syncthreads();   // protect smem reuse by the reduction below

    // ---------------- epilogue ----------------
    // Warp tile: rows utile + wu*32 + rg*16 + {rl0, rl0+8}; cols ws*64 + nt*8 + 2*tig.
    const int rl0 = lane >> 2;
    const int tig = lane & 3;
    float* red = (float*)smem;   // z: [0,512), am: [512,1024)

    #pragma unroll
    for (int rg = 0; rg < 2; rg++) {
        float (*acc)[4] = rg ? acc1 : acc0;
        const int ul0 = wu * 32 + rg * 16 + rl0;
        const int ul1 = ul0 + 8;
        const int r0  = b * MAXLEN + utile + ul0;
        const int r1  = b * MAXLEN + utile + ul1;

        unsigned w0[2], w1[2];
        #pragma unroll
        for (int q = 0; q < 2; q++) {
            w0[q] = g_maskbits[r0 * NWORDS + ws * 2 + q];
            w1[q] = g_maskbits[r1 * NWORDS + ws * 2 + q];
        }
        // Consume-and-clear: each (row, word) owned by exactly one warp's tig==0
        // lane. Leaves the bitmap all-zero for the next invocation.
        if (tig == 0) {
            #pragma unroll
            for (int q = 0; q < 2; q++) {
                g_maskbits[r0 * NWORDS + ws * 2 + q] = 0u;
                g_maskbits[r1 * NWORDS + ws * 2 + q] = 0u;
            }
        }

        float z0 = 0.f, am0 = 0.f, z1 = 0.f, am1 = 0.f;
        #pragma unroll
        for (int nt = 0; nt < 8; nt++) {
            const int q   = nt >> 2;
            const int bit = (nt & 3) * 8 + 2 * tig;
            float e0 = __expf(acc[nt][0]);
            float e1 = __expf(acc[nt][1]);
            float e2 = __expf(acc[nt][2]);
            float e3 = __expf(acc[nt][3]);
            acc[nt][0] = e0; acc[nt][1] = e1; acc[nt][2] = e2; acc[nt][3] = e3;
            z0 += e0 + e1; z1 += e2 + e3;
            if ((w0[q] >> bit)       & 1u) am0 += e0;
            if ((w0[q] >> (bit + 1)) & 1u) am0 += e1;
            if ((w1[q] >> bit)       & 1u) am1 += e2;
            if ((w1[q] >> (bit + 1)) & 1u) am1 += e3;
        }
        #pragma unroll
        for (int o = 1; o <= 2; o <<= 1) {
            z0  += __shfl_xor_sync(0xffffffffu, z0,  o);
            am0 += __shfl_xor_sync(0xffffffffu, am0, o);
            z1  += __shfl_xor_sync(0xffffffffu, z1,  o);
            am1 += __shfl_xor_sync(0xffffffffu, am1, o);
        }

        if (rg) __syncthreads();   // reuse red buffer between row-groups
        if (tig == 0) {
            red[ws * 64 + ul0]       = z0;
            red[ws * 64 + ul1]       = z1;
            red[512 + ws * 64 + ul0] = am0;
            red[512 + ws * 64 + ul1] = am1;
        }
        __syncthreads();
        float zs0 = 0.f, as0 = 0.f, zs1 = 0.f, as1 = 0.f;
        #pragma unroll
        for (int w = 0; w < 8; w++) {
            zs0 += red[w * 64 + ul0];       as0 += red[512 + w * 64 + ul0];
            zs1 += red[w * 64 + ul1];       as1 += red[512 + w * 64 + ul1];
        }
        const float inv0 = 1.0f / (as0 + 1e-10f * (zs0 - as0));
        const float inv1 = 1.0f / (as1 + 1e-10f * (zs1 - as1));

        #pragma unroll
        for (int nt = 0; nt < 8; nt++) {
            const int q   = nt >> 2;
            const int bit = (nt & 3) * 8 + 2 * tig;
            const int sc  = ws * 64 + nt * 8 + 2 * tig;
            float2 v0, v1;
            v0.x = ((w0[q] >> bit)       & 1u) ? acc[nt][0] * inv0 : 0.f;
            v0.y = ((w0[q] >> (bit + 1)) & 1u) ? acc[nt][1] * inv0 : 0.f;
            v1.x = ((w1[q] >> bit)       & 1u) ? acc[nt][2] * inv1 : 0.f;
            v1.y = ((w1[q] >> (bit + 1)) & 1u) ? acc[nt][3] * inv1 : 0.f;
            *(float2*)&out[(size_t)r0 * SEQ + sc] = v0;
            *(float2*)&out[(size_t)r1 * SEQ + sc] = v1;
        }
    }
}

extern "C" void kernel_launch(void* const* d_in, const int* in_sizes, int n_in,
                              void* d_out, int out_size) {
    const float* M  = (const float*)d_in[0];
    const float* W  = (const float*)d_in[1];
    const int*   eb = (const int*)d_in[3];
    const int*   eu = (const int*)d_in[4];
    const int*   ev = (const int*)d_in[5];
    const int    E  = in_sizes[3];
    float* out = (float*)d_out;

    cudaFuncSetAttribute(mea_mma_kernel,
                         cudaFuncAttributeMaxDynamicSharedMemorySize, SM_TOTAL);

    const int edgeBlocks = (E + PREP_T - 1) / PREP_T;
    const int prepBlocks = edgeBlocks + CONVM_ITEMS / PREP_T
                         + (CONVW_ITEMS + PREP_T - 1) / PREP_T;
    prep_kernel<<<prepBlocks, PREP_T>>>(eb, eu, ev, E, edgeBlocks, M, W);
    mea_mma_kernel<<<dim3(MAXLEN / UTILE, BATCH), MMA_T, SM_TOTAL>>>(out);
}

// round 13
// speedup vs baseline: 1.1756x; 1.1756x over previous
#include <cuda_runtime.h>
#include <cuda_fp16.h>
#include <cstdint>

#define SEQ    512
#define BATCH  64
#define DIM    512
#define MAXLEN 512
#define NWORDS (SEQ/32)

#define UTILE   32            // u rows per CTA
#define KCHUNK  32            // fp32 k elems per chunk -> 64B fp16 row
#define NCHUNKS (DIM/KCHUNK)  // 16
#define KSTEPS  2             // two k=16 MMA steps per chunk

// ---- stage layout (bytes), 64B rows ----
#define SM_A      0                       // 32 rows x 64B = 2 KB
#define SM_B      2048                    // 512 rows x 64B = 32 KB
#define STAGE_BYTES 34816
#define NSTAGES   3
#define SM_TOTAL  (NSTAGES*STAGE_BYTES)   // 104448  -> 2 CTAs/SM

#define PREP_T   256
#define MMA_T    256          // 8 warps: 2(u) x 4(s)

#define CONVM_ITEMS (BATCH * NCHUNKS * SEQ * 4)   // 2097152
#define CONVW_ITEMS (NCHUNKS * MAXLEN * 4)        // 32768

// ---- persistent device scratch ----
// gMc: [b][ck][s][64B fp16] ; gWc: [ck][u][64B fp16]
__device__ uint4 gMc[BATCH * NCHUNKS * SEQ * 4];   // 32 MB
__device__ uint4 gWc[NCHUNKS * MAXLEN * 4];        // 512 KB
// Zero at module load; mea_mma's epilogue re-zeroes every word it consumes,
// so every invocation (correctness run + each graph replay) leaves it zeroed.
__device__ unsigned g_maskbits[BATCH * MAXLEN * NWORDS];

// One kernel: mask-build + conv_M + conv_W, block-range partitioned.
__global__ void prep_kernel(const int* __restrict__ eb,
                            const int* __restrict__ eu,
                            const int* __restrict__ ev, int E, int edgeBlocks,
                            const float* __restrict__ Mm,
                            const float* __restrict__ Wm) {
    const int bid = blockIdx.x;
    const int tid = threadIdx.x;

    if (bid < edgeBlocks) {                     // ---- build mask ----
        int i = bid * PREP_T + tid;
        if (i < E)
            atomicOr(&g_maskbits[(eb[i] * MAXLEN + eu[i]) * NWORDS + (ev[i] >> 5)],
                     1u << (ev[i] & 31));
        return;
    }
    int b2 = bid - edgeBlocks;
    if (b2 < CONVM_ITEMS / PREP_T) {            // ---- conv M -> fp16 64B rows ----
        int i = b2 * PREP_T + tid;
        int f4 = i & 3, s = (i >> 2) & 511, ck = (i >> 11) & 15, b = i >> 15;
        const float* src = &Mm[((size_t)s * BATCH + b) * DIM + ck * KCHUNK + f4 * 8];
        float4 v0 = *(const float4*)src;
        float4 v1 = *(const float4*)(src + 4);
        __half2 h0 = __floats2half2_rn(v0.x, v0.y);
        __half2 h1 = __floats2half2_rn(v0.z, v0.w);
        __half2 h2 = __floats2half2_rn(v1.x, v1.y);
        __half2 h3 = __floats2half2_rn(v1.z, v1.w);
        uint4 o; o.x = *(uint32_t*)&h0; o.y = *(uint32_t*)&h1;
                 o.z = *(uint32_t*)&h2; o.w = *(uint32_t*)&h3;
        *(uint4*)((char*)gMc + ((size_t)((b * NCHUNKS + ck) * SEQ + s)) * 64 + f4 * 16) = o;
        return;
    }
    int b3 = b2 - CONVM_ITEMS / PREP_T;         // ---- conv W -> fp16 64B rows ----
    {
        int i = b3 * PREP_T + tid;
        if (i >= CONVW_ITEMS) return;
        int f4 = i & 3, u = (i >> 2) & 511, ck = i >> 11;
        const float* src = &Wm[(size_t)u * DIM + ck * KCHUNK + f4 * 8];
        float4 v0 = *(const float4*)src;
        float4 v1 = *(const float4*)(src + 4);
        __half2 h0 = __floats2half2_rn(v0.x, v0.y);
        __half2 h1 = __floats2half2_rn(v0.z, v0.w);
        __half2 h2 = __floats2half2_rn(v1.x, v1.y);
        __half2 h3 = __floats2half2_rn(v1.z, v1.w);
        uint4 o; o.x = *(uint32_t*)&h0; o.y = *(uint32_t*)&h1;
                 o.z = *(uint32_t*)&h2; o.w = *(uint32_t*)&h3;
        *(uint4*)((char*)gWc + ((size_t)(ck * MAXLEN + u)) * 64 + f4 * 16) = o;
    }
}

// ---------------- helpers ----------------
__device__ __forceinline__ uint32_t smem_u32(const void* p) {
    uint32_t a;
    asm("{ .reg .u64 t; cvta.to.shared.u64 t, %1; cvt.u32.u64 %0, t; }" : "=r"(a) : "l"(p));
    return a;
}
// SW64 swizzle for 64-byte rows: bits[5:4] ^= bits[9:8]>>... = (off>>3)&0x30
__device__ __forceinline__ uint32_t sw64(uint32_t off) { return off ^ ((off >> 3) & 0x30); }

__device__ __forceinline__ void ldsm_x4(uint32_t& r0, uint32_t& r1,
                                        uint32_t& r2, uint32_t& r3, uint32_t addr) {
    asm volatile("ldmatrix.sync.aligned.m8n8.x4.shared.b16 {%0,%1,%2,%3}, [%4];"
                 : "=r"(r0), "=r"(r1), "=r"(r2), "=r"(r3) : "r"(addr));
}

__device__ __forceinline__ void mma16816(float* d, const uint32_t* a,
                                         uint32_t b0, uint32_t b1) {
    asm volatile("mma.sync.aligned.m16n8k16.row.col.f32.f16.f16.f32 "
                 "{%0,%1,%2,%3}, {%4,%5,%6,%7}, {%8,%9}, {%0,%1,%2,%3};"
                 : "+f"(d[0]), "+f"(d[1]), "+f"(d[2]), "+f"(d[3])
                 : "r"(a[0]), "r"(a[1]), "r"(a[2]), "r"(a[3]), "r"(b0), "r"(b1));
}

__device__ __forceinline__ void cp16(uint32_t dst, const void* src) {
    asm volatile("cp.async.cg.shared.global [%0], [%1], 16;" :: "r"(dst), "l"(src));
}

__device__ __forceinline__ void load_stage(uint32_t sb, int stage, int ck,
                                           int b, int utile, int tid) {
    const uint32_t sbase = sb + stage * STAGE_BYTES;
    const char* srcB = (const char*)gMc + ((size_t)((b * NCHUNKS + ck) * SEQ)) * 64;
    #pragma unroll
    for (int it = 0; it < 8; it++) {
        int idx = it * MMA_T + tid;
        int s = idx >> 2, f4 = idx & 3;
        cp16(sbase + SM_B + sw64((uint32_t)(s * 64 + f4 * 16)),
             srcB + s * 64 + f4 * 16);
    }
    if (tid < 128) {
        int u = tid >> 2, f4 = tid & 3;
        cp16(sbase + SM_A + sw64((uint32_t)(u * 64 + f4 * 16)),
             (const char*)gWc + ((size_t)(ck * MAXLEN + utile + u)) * 64 + f4 * 16);
    }
    asm volatile("cp.async.commit_group;");
}

__global__ __launch_bounds__(MMA_T, 2)
void mea_mma_kernel(float* __restrict__ out) {    // (BATCH, MAXLEN, SEQ)
    extern __shared__ char smem[];
    const uint32_t sb = smem_u32(smem);
    const int tid  = threadIdx.x;
    const int wid  = tid >> 5;
    const int lane = tid & 31;
    const int wu   = wid >> 2;      // 0..1 : u-slice (16 rows)
    const int ws   = wid & 3;       // 0..3 : s-slice (128 cols)
    const int b     = blockIdx.y;
    const int utile = blockIdx.x * UTILE;

    // ldmatrix per-lane address components (SW64, 64B rows).
    // XOR field = ((row>>1)&3)<<4; row steps of 16 don't change it.
    const int a_kh  = (lane >> 4) * 16;
    const int xrA   = ((((lane & 15)) >> 1) & 3) << 4;
    const int b_rowl = ((lane >> 4) << 3) + (lane & 7);
    const int b_kh   = ((lane >> 3) & 1) << 4;
    const int xrB    = ((b_rowl >> 1) & 3) << 4;
    const uint32_t aRow = (uint32_t)((wu * 16 + (lane & 15)) * 64);
    const uint32_t bRow = (uint32_t)(SM_B + (ws * 128 + b_rowl) * 64);

    float acc[16][4];   // 16 n-tiles x (rows rl0, rl0+8)
    #pragma unroll
    for (int nt = 0; nt < 16; nt++)
        #pragma unroll
        for (int j = 0; j < 4; j++) acc[nt][j] = 0.f;

    load_stage(sb, 0, 0, b, utile, tid);
    load_stage(sb, 1, 1, b, utile, tid);

    #pragma unroll 1
    for (int ck = 0; ck < NCHUNKS; ck++) {
        if (ck == NCHUNKS - 1) asm volatile("cp.async.wait_group 0;" ::: "memory");
        else                   asm volatile("cp.async.wait_group 1;" ::: "memory");
        __syncthreads();
        if (ck + 2 < NCHUNKS)
            load_stage(sb, (ck + 2) % NSTAGES, ck + 2, b, utile, tid);

        const uint32_t sbase = sb + (ck % NSTAGES) * STAGE_BYTES;
        const uint32_t aB = sbase + SM_A + aRow;
        const uint32_t bB = sbase + bRow;

        #pragma unroll
        for (int ks = 0; ks < KSTEPS; ks++) {
            const uint32_t ac = (uint32_t)((ks * 32 + a_kh) ^ xrA);
            const uint32_t bc = (uint32_t)((ks * 32 + b_kh) ^ xrB);
            uint32_t a[4];
            ldsm_x4(a[0], a[1], a[2], a[3], aB + ac);
            #pragma unroll
            for (int np = 0; np < 8; np++) {
                uint32_t b0, b1, b2, b3;
                ldsm_x4(b0, b1, b2, b3, bB + np * 1024 + bc);
                mma16816(acc[2*np+0], a, b0, b1);
                mma16816(acc[2*np+1], a, b2, b3);
            }
        }
    }
    __syncthreads();   // protect smem reuse by the reduction below

    // ---------------- epilogue ----------------
    // Warp tile: rows utile + wu*16 + {rl0, rl0+8}; cols ws*128 + nt*8 + 2*tig.
    const int rl0 = lane >> 2;
    const int tig = lane & 3;
    const int ul0 = wu * 16 + rl0;
    const int ul1 = ul0 + 8;
    const int r0  = b * MAXLEN + utile + ul0;
    const int r1  = b * MAXLEN + utile + ul1;
    float* red = (float*)smem;   // z: [0,128), am: [128,256)

    unsigned w0[4], w1[4];
    #pragma unroll
    for (int q = 0; q < 4; q++) {
        w0[q] = g_maskbits[r0 * NWORDS + ws * 4 + q];
        w1[q] = g_maskbits[r1 * NWORDS + ws * 4 + q];
    }
    // Consume-and-clear: each (row, word) owned by exactly one warp's tig==0
    // lane. Leaves the bitmap all-zero for the next invocation.
    if (tig == 0) {
        #pragma unroll
        for (int q = 0; q < 4; q++) {
            g_maskbits[r0 * NWORDS + ws * 4 + q] = 0u;
            g_maskbits[r1 * NWORDS + ws * 4 + q] = 0u;
        }
    }

    float z0 = 0.f, am0 = 0.f, z1 = 0.f, am1 = 0.f;
    #pragma unroll
    for (int nt = 0; nt < 16; nt++) {
        const int q   = nt >> 2;
        const int bit = (nt & 3) * 8 + 2 * tig;
        float e0 = __expf(acc[nt][0]);
        float e1 = __expf(acc[nt][1]);
        float e2 = __expf(acc[nt][2]);
        float e3 = __expf(acc[nt][3]);
        acc[nt][0] = e0; acc[nt][1] = e1; acc[nt][2] = e2; acc[nt][3] = e3;
        z0 += e0 + e1; z1 += e2 + e3;
        if ((w0[q] >> bit)       & 1u) am0 += e0;
        if ((w0[q] >> (bit + 1)) & 1u) am0 += e1;
        if ((w1[q] >> bit)       & 1u) am1 += e2;
        if ((w1[q] >> (bit + 1)) & 1u) am1 += e3;
    }
    #pragma unroll
    for (int o = 1; o <= 2; o <<= 1) {
        z0  += __shfl_xor_sync(0xffffffffu, z0,  o);
        am0 += __shfl_xor_sync(0xffffffffu, am0, o);
        z1  += __shfl_xor_sync(0xffffffffu, z1,  o);
        am1 += __shfl_xor_sync(0xffffffffu, am1, o);
    }

    if (tig == 0) {
        red[ws * 32 + ul0]       = z0;
        red[ws * 32 + ul1]       = z1;
        red[128 + ws * 32 + ul0] = am0;
        red[128 + ws * 32 + ul1] = am1;
    }
    __syncthreads();
    float zs0 = 0.f, as0 = 0.f, zs1 = 0.f, as1 = 0.f;
    #pragma unroll
    for (int w = 0; w < 4; w++) {
        zs0 += red[w * 32 + ul0];       as0 += red[128 + w * 32 + ul0];
        zs1 += red[w * 32 + ul1];       as1 += red[128 + w * 32 + ul1];
    }
    const float inv0 = 1.0f / (as0 + 1e-10f * (zs0 - as0));
    const float inv1 = 1.0f / (as1 + 1e-10f * (zs1 - as1));

    #pragma unroll
    for (int nt = 0; nt < 16; nt++) {
        const int q   = nt >> 2;
        const int bit = (nt & 3) * 8 + 2 * tig;
        const int sc  = ws * 128 + nt * 8 + 2 * tig;
        float2 v0, v1;
        v0.x = ((w0[q] >> bit)       & 1u) ? acc[nt][0] * inv0 : 0.f;
        v0.y = ((w0[q] >> (bit + 1)) & 1u) ? acc[nt][1] * inv0 : 0.f;
        v1.x = ((w1[q] >> bit)       & 1u) ? acc[nt][2] * inv1 : 0.f;
        v1.y = ((w1[q] >> (bit + 1)) & 1u) ? acc[nt][3] * inv1 : 0.f;
        *(float2*)&out[(size_t)r0 * SEQ + sc] = v0;
        *(float2*)&out[(size_t)r1 * SEQ + sc] = v1;
    }
}

extern "C" void kernel_launch(void* const* d_in, const int* in_sizes, int n_in,
                              void* d_out, int out_size) {
    const float* M  = (const float*)d_in[0];
    const float* W  = (const float*)d_in[1];
    const int*   eb = (const int*)d_in[3];
    const int*   eu = (const int*)d_in[4];
    const int*   ev = (const int*)d_in[5];
    const int    E  = in_sizes[3];
    float* out = (float*)d_out;

    cudaFuncSetAttribute(mea_mma_kernel,
                         cudaFuncAttributeMaxDynamicSharedMemorySize, SM_TOTAL);

    const int edgeBlocks = (E + PREP_T - 1) / PREP_T;
    const int prepBlocks = edgeBlocks + CONVM_ITEMS / PREP_T
                         + (CONVW_ITEMS + PREP_T - 1) / PREP_T;
    prep_kernel<<<prepBlocks, PREP_T>>>(eb, eu, ev, E, edgeBlocks, M, W);
    mea_mma_kernel<<<dim3(MAXLEN / UTILE, BATCH), MMA_T, SM_TOTAL>>>(out);
}

// round 14
// speedup vs baseline: 1.2048x; 1.0248x over previous
#include <cuda_runtime.h>
#include <cuda_fp16.h>
#include <cstdint>

#define SEQ    512
#define BATCH  64
#define DIM    512
#define MAXLEN 512
#define NWORDS (SEQ/32)

#define UTILE   32            // u rows per CTA
#define KCHUNK  32            // fp32 k elems per chunk -> 64B fp16 row
#define NCHUNKS (DIM/KCHUNK)  // 16
#define KSTEPS  2             // two k=16 MMA steps per chunk

// ---- stage layout (bytes), 64B rows ----
#define SM_A      0                       // 32 rows x 64B = 2 KB
#define SM_B      2048                    // 512 rows x 64B = 32 KB
#define STAGE_BYTES 34816
#define NSTAGES   3
#define SM_TOTAL  (NSTAGES*STAGE_BYTES)   // 104448  -> 2 CTAs/SM

#define PREP_T   256
#define MMA_T    256          // 8 warps: 1(u) x 8(s), warp tile 32u x 64s

#define CONVM_ITEMS (BATCH * NCHUNKS * SEQ * 4)   // 2097152
#define CONVW_ITEMS (NCHUNKS * MAXLEN * 4)        // 32768

// ---- persistent device scratch ----
// gMc: [b][ck][s][64B fp16] ; gWc: [ck][u][64B fp16]
__device__ uint4 gMc[BATCH * NCHUNKS * SEQ * 4];   // 32 MB
__device__ uint4 gWc[NCHUNKS * MAXLEN * 4];        // 512 KB
// Zero at module load; mea_mma's epilogue re-zeroes every word it consumes,
// so every invocation (correctness run + each graph replay) leaves it zeroed.
__device__ unsigned g_maskbits[BATCH * MAXLEN * NWORDS];

// One kernel: mask-build + conv_M + conv_W, block-range partitioned.
__global__ void prep_kernel(const int* __restrict__ eb,
                            const int* __restrict__ eu,
                            const int* __restrict__ ev, int E, int edgeBlocks,
                            const float* __restrict__ Mm,
                            const float* __restrict__ Wm) {
    const int bid = blockIdx.x;
    const int tid = threadIdx.x;

    if (bid < edgeBlocks) {                     // ---- build mask ----
        int i = bid * PREP_T + tid;
        if (i < E)
            atomicOr(&g_maskbits[(eb[i] * MAXLEN + eu[i]) * NWORDS + (ev[i] >> 5)],
                     1u << (ev[i] & 31));
        return;
    }
    int b2 = bid - edgeBlocks;
    if (b2 < CONVM_ITEMS / PREP_T) {            // ---- conv M -> fp16 64B rows ----
        int i = b2 * PREP_T + tid;
        int f4 = i & 3, s = (i >> 2) & 511, ck = (i >> 11) & 15, b = i >> 15;
        const float* src = &Mm[((size_t)s * BATCH + b) * DIM + ck * KCHUNK + f4 * 8];
        float4 v0 = *(const float4*)src;
        float4 v1 = *(const float4*)(src + 4);
        __half2 h0 = __floats2half2_rn(v0.x, v0.y);
        __half2 h1 = __floats2half2_rn(v0.z, v0.w);
        __half2 h2 = __floats2half2_rn(v1.x, v1.y);
        __half2 h3 = __floats2half2_rn(v1.z, v1.w);
        uint4 o; o.x = *(uint32_t*)&h0; o.y = *(uint32_t*)&h1;
                 o.z = *(uint32_t*)&h2; o.w = *(uint32_t*)&h3;
        *(uint4*)((char*)gMc + ((size_t)((b * NCHUNKS + ck) * SEQ + s)) * 64 + f4 * 16) = o;
        return;
    }
    int b3 = b2 - CONVM_ITEMS / PREP_T;         // ---- conv W -> fp16 64B rows ----
    {
        int i = b3 * PREP_T + tid;
        if (i >= CONVW_ITEMS) return;
        int f4 = i & 3, u = (i >> 2) & 511, ck = i >> 11;
        const float* src = &Wm[(size_t)u * DIM + ck * KCHUNK + f4 * 8];
        float4 v0 = *(const float4*)src;
        float4 v1 = *(const float4*)(src + 4);
        __half2 h0 = __floats2half2_rn(v0.x, v0.y);
        __half2 h1 = __floats2half2_rn(v0.z, v0.w);
        __half2 h2 = __floats2half2_rn(v1.x, v1.y);
        __half2 h3 = __floats2half2_rn(v1.z, v1.w);
        uint4 o; o.x = *(uint32_t*)&h0; o.y = *(uint32_t*)&h1;
                 o.z = *(uint32_t*)&h2; o.w = *(uint32_t*)&h3;
        *(uint4*)((char*)gWc + ((size_t)(ck * MAXLEN + u)) * 64 + f4 * 16) = o;
    }
}

// ---------------- helpers ----------------
__device__ __forceinline__ uint32_t smem_u32(const void* p) {
    uint32_t a;
    asm("{ .reg .u64 t; cvta.to.shared.u64 t, %1; cvt.u32.u64 %0, t; }" : "=r"(a) : "l"(p));
    return a;
}
// SW64 swizzle for 64-byte rows
__device__ __forceinline__ uint32_t sw64(uint32_t off) { return off ^ ((off >> 3) & 0x30); }

__device__ __forceinline__ void ldsm_x4(uint32_t& r0, uint32_t& r1,
                                        uint32_t& r2, uint32_t& r3, uint32_t addr) {
    asm volatile("ldmatrix.sync.aligned.m8n8.x4.shared.b16 {%0,%1,%2,%3}, [%4];"
                 : "=r"(r0), "=r"(r1), "=r"(r2), "=r"(r3) : "r"(addr));
}

__device__ __forceinline__ void mma16816(float* d, const uint32_t* a,
                                         uint32_t b0, uint32_t b1) {
    asm volatile("mma.sync.aligned.m16n8k16.row.col.f32.f16.f16.f32 "
                 "{%0,%1,%2,%3}, {%4,%5,%6,%7}, {%8,%9}, {%0,%1,%2,%3};"
                 : "+f"(d[0]), "+f"(d[1]), "+f"(d[2]), "+f"(d[3])
                 : "r"(a[0]), "r"(a[1]), "r"(a[2]), "r"(a[3]), "r"(b0), "r"(b1));
}

__device__ __forceinline__ void cp16(uint32_t dst, const void* src) {
    asm volatile("cp.async.cg.shared.global [%0], [%1], 16;" :: "r"(dst), "l"(src));
}

__device__ __forceinline__ void load_stage(uint32_t sb, int stage, int ck,
                                           int b, int utile, int tid) {
    const uint32_t sbase = sb + stage * STAGE_BYTES;
    const char* srcB = (const char*)gMc + ((size_t)((b * NCHUNKS + ck) * SEQ)) * 64;
    #pragma unroll
    for (int it = 0; it < 8; it++) {
        int idx = it * MMA_T + tid;
        int s = idx >> 2, f4 = idx & 3;
        cp16(sbase + SM_B + sw64((uint32_t)(s * 64 + f4 * 16)),
             srcB + s * 64 + f4 * 16);
    }
    if (tid < 128) {
        int u = tid >> 2, f4 = tid & 3;
        cp16(sbase + SM_A + sw64((uint32_t)(u * 64 + f4 * 16)),
             (const char*)gWc + ((size_t)(ck * MAXLEN + utile + u)) * 64 + f4 * 16);
    }
    asm volatile("cp.async.commit_group;");
}

__global__ __launch_bounds__(MMA_T, 2)
void mea_mma_kernel(float* __restrict__ out) {    // (BATCH, MAXLEN, SEQ)
    extern __shared__ char smem[];
    const uint32_t sb = smem_u32(smem);
    const int tid  = threadIdx.x;
    const int wid  = tid >> 5;
    const int lane = tid & 31;
    const int ws   = wid;           // 0..7 : s-slice (64 cols); warp covers all 32 u
    const int b     = blockIdx.y;
    const int utile = blockIdx.x * UTILE;

    // ldmatrix per-lane address components (SW64, 64B rows).
    // A XOR field = ((row>>1)&3)<<4; +16 rows leaves it unchanged (16>>1 = 8, 8&3=0).
    const int a_kh  = (lane >> 4) * 16;
    const int xrA   = (((lane & 15) >> 1) & 3) << 4;
    const int b_rowl = ((lane >> 4) << 3) + (lane & 7);
    const int b_kh   = ((lane >> 3) & 1) << 4;
    const int xrB    = ((b_rowl >> 1) & 3) << 4;
    const uint32_t aRow0 = (uint32_t)((lane & 15) * 64);        // u rows 0..15
    const uint32_t aRow1 = aRow0 + 16 * 64;                     // u rows 16..31
    const uint32_t bRow  = (uint32_t)(SM_B + (ws * 64 + b_rowl) * 64);

    float acc0[8][4], acc1[8][4];   // u rows 0..15 / 16..31, 8 n-tiles of 8 s-cols
    #pragma unroll
    for (int nt = 0; nt < 8; nt++)
        #pragma unroll
        for (int j = 0; j < 4; j++) { acc0[nt][j] = 0.f; acc1[nt][j] = 0.f; }

    load_stage(sb, 0, 0, b, utile, tid);
    load_stage(sb, 1, 1, b, utile, tid);

    #pragma unroll 1
    for (int ck = 0; ck < NCHUNKS; ck++) {
        if (ck == NCHUNKS - 1) asm volatile("cp.async.wait_group 0;" ::: "memory");
        else                   asm volatile("cp.async.wait_group 1;" ::: "memory");
        __syncthreads();
        if (ck + 2 < NCHUNKS)
            load_stage(sb, (ck + 2) % NSTAGES, ck + 2, b, utile, tid);

        const uint32_t sbase = sb + (ck % NSTAGES) * STAGE_BYTES;
        const uint32_t aB0 = sbase + SM_A + aRow0;
        const uint32_t aB1 = sbase + SM_A + aRow1;
        const uint32_t bB  = sbase + bRow;

        #pragma unroll
        for (int ks = 0; ks < KSTEPS; ks++) {
            const uint32_t ac = (uint32_t)((ks * 32 + a_kh) ^ xrA);
            const uint32_t bc = (uint32_t)((ks * 32 + b_kh) ^ xrB);
            uint32_t a0[4], a1[4];
            ldsm_x4(a0[0], a0[1], a0[2], a0[3], aB0 + ac);
            ldsm_x4(a1[0], a1[1], a1[2], a1[3], aB1 + ac);
            #pragma unroll
            for (int np = 0; np < 4; np++) {
                uint32_t b0, b1, b2, b3;
                ldsm_x4(b0, b1, b2, b3, bB + np * 1024 + bc);
                mma16816(acc0[2*np+0], a0, b0, b1);
                mma16816(acc0[2*np+1], a0, b2, b3);
                mma16816(acc1[2*np+0], a1, b0, b1);
                mma16816(acc1[2*np+1], a1, b2, b3);
            }
        }
    }
    __syncthreads();   // protect smem reuse by the reduction below

    // ---------------- epilogue ----------------
    // Thread owns 4 rows: rl0, rl0+8 (acc0) and rl0+16, rl0+24 (acc1);
    // cols sc = ws*64 + nt*8 + 2*tig + {0,1}.
    const int rl0 = lane >> 2;
    const int tig = lane & 3;
    float* red = (float*)smem;   // z: [0,256), am: [256,512)

    int rows[4];
    rows[0] = rl0; rows[1] = rl0 + 8; rows[2] = rl0 + 16; rows[3] = rl0 + 24;

    unsigned wmask[4][2];
    #pragma unroll
    for (int j = 0; j < 4; j++) {
        int r = b * MAXLEN + utile + rows[j];
        wmask[j][0] = g_maskbits[r * NWORDS + ws * 2 + 0];
        wmask[j][1] = g_maskbits[r * NWORDS + ws * 2 + 1];
    }
    // Consume-and-clear: each (row, word) owned by exactly one warp's tig==0
    // lane. Leaves the bitmap all-zero for the next invocation.
    if (tig == 0) {
        #pragma unroll
        for (int j = 0; j < 4; j++) {
            int r = b * MAXLEN + utile + rows[j];
            g_maskbits[r * NWORDS + ws * 2 + 0] = 0u;
            g_maskbits[r * NWORDS + ws * 2 + 1] = 0u;
        }
    }

    float zz[4] = {0.f, 0.f, 0.f, 0.f}, aa[4] = {0.f, 0.f, 0.f, 0.f};
    #pragma unroll
    for (int rg = 0; rg < 2; rg++) {
        float (*acc)[4] = rg ? acc1 : acc0;
        #pragma unroll
        for (int nt = 0; nt < 8; nt++) {
            const int q   = nt >> 2;
            const int bit = (nt & 3) * 8 + 2 * tig;
            float e0 = __expf(acc[nt][0]);
            float e1 = __expf(acc[nt][1]);
            float e2 = __expf(acc[nt][2]);
            float e3 = __expf(acc[nt][3]);
            acc[nt][0] = e0; acc[nt][1] = e1; acc[nt][2] = e2; acc[nt][3] = e3;
            zz[2*rg]   += e0 + e1;
            zz[2*rg+1] += e2 + e3;
            if ((wmask[2*rg][q]   >> bit)       & 1u) aa[2*rg]   += e0;
            if ((wmask[2*rg][q]   >> (bit + 1)) & 1u) aa[2*rg]   += e1;
            if ((wmask[2*rg+1][q] >> bit)       & 1u) aa[2*rg+1] += e2;
            if ((wmask[2*rg+1][q] >> (bit + 1)) & 1u) aa[2*rg+1] += e3;
        }
    }
    #pragma unroll
    for (int o = 1; o <= 2; o <<= 1) {
        #pragma unroll
        for (int j = 0; j < 4; j++) {
            zz[j] += __shfl_xor_sync(0xffffffffu, zz[j], o);
            aa[j] += __shfl_xor_sync(0xffffffffu, aa[j], o);
        }
    }

    if (tig == 0) {
        #pragma unroll
        for (int j = 0; j < 4; j++) {
            red[ws * 32 + rows[j]]       = zz[j];
            red[256 + ws * 32 + rows[j]] = aa[j];
        }
    }
    __syncthreads();

    float inv[4];
    #pragma unroll
    for (int j = 0; j < 4; j++) {
        float zs = 0.f, as = 0.f;
        #pragma unroll
        for (int w = 0; w < 8; w++) {
            zs += red[w * 32 + rows[j]];
            as += red[256 + w * 32 + rows[j]];
        }
        inv[j] = 1.0f / (as + 1e-10f * (zs - as));
    }

    #pragma unroll
    for (int rg = 0; rg < 2; rg++) {
        float (*acc)[4] = rg ? acc1 : acc0;
        const int r0 = b * MAXLEN + utile + rows[2*rg];
        const int r1 = b * MAXLEN + utile + rows[2*rg+1];
        #pragma unroll
        for (int nt = 0; nt < 8; nt++) {
            const int q   = nt >> 2;
            const int bit = (nt & 3) * 8 + 2 * tig;
            const int sc  = ws * 64 + nt * 8 + 2 * tig;
            float2 v0, v1;
            v0.x = ((wmask[2*rg][q]   >> bit)       & 1u) ? acc[nt][0] * inv[2*rg]   : 0.f;
            v0.y = ((wmask[2*rg][q]   >> (bit + 1)) & 1u) ? acc[nt][1] * inv[2*rg]   : 0.f;
            v1.x = ((wmask[2*rg+1][q] >> bit)       & 1u) ? acc[nt][2] * inv[2*rg+1] : 0.f;
            v1.y = ((wmask[2*rg+1][q] >> (bit + 1)) & 1u) ? acc[nt][3] * inv[2*rg+1] : 0.f;
            *(float2*)&out[(size_t)r0 * SEQ + sc] = v0;
            *(float2*)&out[(size_t)r1 * SEQ + sc] = v1;
        }
    }
}

extern "C" void kernel_launch(void* const* d_in, const int* in_sizes, int n_in,
                              void* d_out, int out_size) {
    const float* M  = (const float*)d_in[0];
    const float* W  = (const float*)d_in[1];
    const int*   eb = (const int*)d_in[3];
    const int*   eu = (const int*)d_in[4];
    const int*   ev = (const int*)d_in[5];
    const int    E  = in_sizes[3];
    float* out = (float*)d_out;

    cudaFuncSetAttribute(mea_mma_kernel,
                         cudaFuncAttributeMaxDynamicSharedMemorySize, SM_TOTAL);

    const int edgeBlocks = (E + PREP_T - 1) / PREP_T;
    const int prepBlocks = edgeBlocks + CONVM_ITEMS / PREP_T
                         + (CONVW_ITEMS + PREP_T - 1) / PREP_T;
    prep_kernel<<<prepBlocks, PREP_T>>>(eb, eu, ev, E, edgeBlocks, M, W);
    mea_mma_kernel<<<dim3(MAXLEN / UTILE, BATCH), MMA_T, SM_TOTAL>>>(out);
}

// round 15
// speedup vs baseline: 1.2060x; 1.0010x over previous
#include <cuda_runtime.h>
#include <cuda_fp16.h>
#include <cstdint>

#define SEQ    512
#define BATCH  64
#define DIM    512
#define MAXLEN 512
#define NWORDS (SEQ/32)

#define UTILE   32            // u rows per CTA
#define KCHUNK  32            // fp32 k elems per chunk -> 64B fp16 row
#define NCHUNKS (DIM/KCHUNK)  // 16

// B: warp-private 64 s-rows x 64B = 4KB per stage, 3 stages per warp
#define WSTAGE     4096
#define NSTAGES    3
#define WREGION    (NSTAGES*WSTAGE)       // 12288 per warp
#define SM_TOTAL   (8*WREGION)            // 98304 -> 2 CTAs/SM

#define PREP_T   256
#define MMA_T    256          // 8 warps: 1(u) x 8(s), warp tile 32u x 64s

#define CONVM_ITEMS (BATCH * NCHUNKS * SEQ * 4)   // 2097152
#define CONVW_ITEMS (NCHUNKS * 16 * 2 * 2 * 32)   // 32768 fragment uint4s

// ---- persistent device scratch ----
// gMc: [b][ck][s][64B fp16]
// gWfrag: [ck][ut][rg][ks][lane] uint4 -> exact mma A-fragment per thread
__device__ uint4 gMc[BATCH * NCHUNKS * SEQ * 4];   // 32 MB
__device__ uint4 gWfrag[CONVW_ITEMS];              // 512 KB
// Zero at module load; mea_mma's epilogue re-zeroes every word it consumes,
// so every invocation (correctness run + each graph replay) leaves it zeroed.
__device__ unsigned g_maskbits[BATCH * MAXLEN * NWORDS];

__device__ __forceinline__ uint32_t packh2(float x, float y) {
    __half2 h = __floats2half2_rn(x, y);
    return *(uint32_t*)&h;
}

// One kernel: mask-build + conv_M + conv_W(fragment pack), block-partitioned.
__global__ void prep_kernel(const int* __restrict__ eb,
                            const int* __restrict__ eu,
                            const int* __restrict__ ev, int E, int edgeBlocks,
                            const float* __restrict__ Mm,
                            const float* __restrict__ Wm) {
    const int bid = blockIdx.x;
    const int tid = threadIdx.x;

    if (bid < edgeBlocks) {                     // ---- build mask ----
        int i = bid * PREP_T + tid;
        if (i < E)
            atomicOr(&g_maskbits[(eb[i] * MAXLEN + eu[i]) * NWORDS + (ev[i] >> 5)],
                     1u << (ev[i] & 31));
        return;
    }
    int b2 = bid - edgeBlocks;
    if (b2 < CONVM_ITEMS / PREP_T) {            // ---- conv M -> fp16 64B rows ----
        int i = b2 * PREP_T + tid;
        int f4 = i & 3, s = (i >> 2) & 511, ck = (i >> 11) & 15, b = i >> 15;
        const float* src = &Mm[((size_t)s * BATCH + b) * DIM + ck * KCHUNK + f4 * 8];
        float4 v0 = *(const float4*)src;
        float4 v1 = *(const float4*)(src + 4);
        uint4 o;
        o.x = packh2(v0.x, v0.y); o.y = packh2(v0.z, v0.w);
        o.z = packh2(v1.x, v1.y); o.w = packh2(v1.z, v1.w);
        *(uint4*)((char*)gMc + ((size_t)((b * NCHUNKS + ck) * SEQ + s)) * 64 + f4 * 16) = o;
        return;
    }
    int b3 = b2 - CONVM_ITEMS / PREP_T;         // ---- conv W -> A fragments ----
    {
        int i = b3 * PREP_T + tid;
        if (i >= CONVW_ITEMS) return;
        int lane = i & 31, ks = (i >> 5) & 1, rg = (i >> 6) & 1,
            ut = (i >> 7) & 15, ck = i >> 11;
        int g = lane >> 2, tig = lane & 3;
        int u0 = ut * 32 + rg * 16 + g;
        int u1 = u0 + 8;
        int k0 = ck * KCHUNK + ks * 16 + tig * 2;
        float2 w00 = *(const float2*)&Wm[(size_t)u0 * DIM + k0];
        float2 w10 = *(const float2*)&Wm[(size_t)u1 * DIM + k0];
        float2 w01 = *(const float2*)&Wm[(size_t)u0 * DIM + k0 + 8];
        float2 w11 = *(const float2*)&Wm[(size_t)u1 * DIM + k0 + 8];
        uint4 o;
        o.x = packh2(w00.x, w00.y);   // a0: row g,   k tig*2
        o.y = packh2(w10.x, w10.y);   // a1: row g+8, k tig*2
        o.z = packh2(w01.x, w01.y);   // a2: row g,   k tig*2+8
        o.w = packh2(w11.x, w11.y);   // a3: row g+8, k tig*2+8
        gWfrag[i] = o;
    }
}

// ---------------- helpers ----------------
__device__ __forceinline__ uint32_t smem_u32(const void* p) {
    uint32_t a;
    asm("{ .reg .u64 t; cvta.to.shared.u64 t, %1; cvt.u32.u64 %0, t; }" : "=r"(a) : "l"(p));
    return a;
}
__device__ __forceinline__ uint32_t sw64(uint32_t off) { return off ^ ((off >> 3) & 0x30); }

__device__ __forceinline__ void ldsm_x4(uint32_t& r0, uint32_t& r1,
                                        uint32_t& r2, uint32_t& r3, uint32_t addr) {
    asm volatile("ldmatrix.sync.aligned.m8n8.x4.shared.b16 {%0,%1,%2,%3}, [%4];"
                 : "=r"(r0), "=r"(r1), "=r"(r2), "=r"(r3) : "r"(addr));
}

__device__ __forceinline__ void mma16816(float* d, const uint32_t* a,
                                         uint32_t b0, uint32_t b1) {
    asm volatile("mma.sync.aligned.m16n8k16.row.col.f32.f16.f16.f32 "
                 "{%0,%1,%2,%3}, {%4,%5,%6,%7}, {%8,%9}, {%0,%1,%2,%3};"
                 : "+f"(d[0]), "+f"(d[1]), "+f"(d[2]), "+f"(d[3])
                 : "r"(a[0]), "r"(a[1]), "r"(a[2]), "r"(a[3]), "r"(b0), "r"(b1));
}

__device__ __forceinline__ void cp16(uint32_t dst, const void* src) {
    asm volatile("cp.async.cg.shared.global [%0], [%1], 16;" :: "r"(dst), "l"(src));
}

// Warp-private B stage load: 64 rows x 64B, 8 cp16/lane + commit.
__device__ __forceinline__ void loadB_warp(uint32_t dstBase, const char* src, int lane) {
    #pragma unroll
    for (int it = 0; it < 8; it++) {
        int idx = it * 32 + lane;
        int r = idx >> 2, f4 = idx & 3;
        cp16(dstBase + sw64((uint32_t)(r * 64 + f4 * 16)), src + r * 64 + f4 * 16);
    }
    asm volatile("cp.async.commit_group;");
}

__device__ __forceinline__ void ldgA(uint4 fr[2][2], int ck, int ut, int lane) {
    const uint4* base = gWfrag + (((size_t)ck * 16 + ut) << 7) + lane;
    fr[0][0] = __ldg(base);       fr[0][1] = __ldg(base + 32);
    fr[1][0] = __ldg(base + 64);  fr[1][1] = __ldg(base + 96);
}

__device__ __forceinline__ void mma_chunk(float acc0[8][4], float acc1[8][4],
                                          uint4 A[2][2], uint32_t bBase,
                                          int b_kh, int xrB) {
    #pragma unroll
    for (int ks = 0; ks < 2; ks++) {
        const uint32_t bc = (uint32_t)((ks * 32 + b_kh) ^ xrB);
        const uint32_t* a0 = (const uint32_t*)&A[0][ks];
        const uint32_t* a1 = (const uint32_t*)&A[1][ks];
        #pragma unroll
        for (int np = 0; np < 4; np++) {
            uint32_t b0, b1, b2, b3;
            ldsm_x4(b0, b1, b2, b3, bBase + np * 1024 + bc);
            mma16816(acc0[2*np+0], a0, b0, b1);
            mma16816(acc0[2*np+1], a0, b2, b3);
            mma16816(acc1[2*np+0], a1, b0, b1);
            mma16816(acc1[2*np+1], a1, b2, b3);
        }
    }
}

#define WAIT1() asm volatile("cp.async.wait_group 1;" ::: "memory")
#define WAIT0() asm volatile("cp.async.wait_group 0;" ::: "memory")

__global__ __launch_bounds__(MMA_T, 2)
void mea_mma_kernel(float* __restrict__ out) {    // (BATCH, MAXLEN, SEQ)
    extern __shared__ char smem[];
    const uint32_t sb = smem_u32(smem);
    const int tid  = threadIdx.x;
    const int ws   = tid >> 5;      // warp = s-slice (64 cols), covers all 32 u
    const int lane = tid & 31;
    const int b     = blockIdx.y;
    const int ut    = blockIdx.x;          // 0..15
    const int utile = ut * UTILE;

    const uint32_t wBase = sb + ws * WREGION;
    const char* srcB0 = (const char*)gMc
        + ((size_t)((b * NCHUNKS) * SEQ + ws * 64)) * 64;   // + ck*SEQ*64

    // ldmatrix B per-lane address components (SW64, 64B rows)
    const int b_rowl = ((lane >> 4) << 3) + (lane & 7);
    const int b_kh   = ((lane >> 3) & 1) << 4;
    const int xrB    = ((b_rowl >> 1) & 3) << 4;
    const uint32_t bRowOff = (uint32_t)(b_rowl * 64);

    float acc0[8][4], acc1[8][4];   // u rows 0..15 / 16..31, 8 n-tiles
    #pragma unroll
    for (int nt = 0; nt < 8; nt++)
        #pragma unroll
        for (int j = 0; j < 4; j++) { acc0[nt][j] = 0.f; acc1[nt][j] = 0.f; }

    uint4 Aeven[2][2], Aodd[2][2];

    // prologue: B stages for chunks 0,1 ; A fragments for chunk 0
    loadB_warp(wBase + 0,      srcB0 + (size_t)0 * SEQ * 64, lane);
    loadB_warp(wBase + WSTAGE, srcB0 + (size_t)1 * SEQ * 64, lane);
    ldgA(Aeven, 0, ut, lane);

    uint32_t cOff = 0, pOff = 2 * WSTAGE;

    #pragma unroll 1
    for (int ck2 = 0; ck2 < NCHUNKS; ck2 += 2) {
        // ---- even chunk ck2 (never the last chunk) ----
        WAIT1(); __syncwarp();
        if (ck2 + 2 < NCHUNKS)
            loadB_warp(wBase + pOff, srcB0 + (size_t)(ck2 + 2) * SEQ * 64, lane);
        ldgA(Aodd, ck2 + 1, ut, lane);
        mma_chunk(acc0, acc1, Aeven, wBase + cOff + bRowOff, b_kh, xrB);
        cOff += WSTAGE; if (cOff == WREGION) cOff = 0;
        pOff += WSTAGE; if (pOff == WREGION) pOff = 0;

        // ---- odd chunk ck2+1 ----
        if (ck2 + 1 == NCHUNKS - 1) { WAIT0(); } else { WAIT1(); }
        __syncwarp();
        if (ck2 + 3 < NCHUNKS)
            loadB_warp(wBase + pOff, srcB0 + (size_t)(ck2 + 3) * SEQ * 64, lane);
        if (ck2 + 2 < NCHUNKS)
            ldgA(Aeven, ck2 + 2, ut, lane);
        mma_chunk(acc0, acc1, Aodd, wBase + cOff + bRowOff, b_kh, xrB);
        cOff += WSTAGE; if (cOff == WREGION) cOff = 0;
        pOff += WSTAGE; if (pOff == WREGION) pOff = 0;
    }
    __syncthreads();   // all warps done with smem before red-buffer reuse

    // ---------------- epilogue (unchanged from R14) ----------------
    const int rl0 = lane >> 2;
    const int tig = lane & 3;
    float* red = (float*)smem;   // z: [0,256), am: [256,512)

    int rows[4];
    rows[0] = rl0; rows[1] = rl0 + 8; rows[2] = rl0 + 16; rows[3] = rl0 + 24;

    unsigned wmask[4][2];
    #pragma unroll
    for (int j = 0; j < 4; j++) {
        int r = b * MAXLEN + utile + rows[j];
        wmask[j][0] = g_maskbits[r * NWORDS + ws * 2 + 0];
        wmask[j][1] = g_maskbits[r * NWORDS + ws * 2 + 1];
    }
    // Consume-and-clear: each (row, word) owned by exactly one warp's tig==0
    // lane. Leaves the bitmap all-zero for the next invocation.
    if (tig == 0) {
        #pragma unroll
        for (int j = 0; j < 4; j++) {
            int r = b * MAXLEN + utile + rows[j];
            g_maskbits[r * NWORDS + ws * 2 + 0] = 0u;
            g_maskbits[r * NWORDS + ws * 2 + 1] = 0u;
        }
    }

    float zz[4] = {0.f, 0.f, 0.f, 0.f}, aa[4] = {0.f, 0.f, 0.f, 0.f};
    #pragma unroll
    for (int rg = 0; rg < 2; rg++) {
        float (*acc)[4] = rg ? acc1 : acc0;
        #pragma unroll
        for (int nt = 0; nt < 8; nt++) {
            const int q   = nt >> 2;
            const int bit = (nt & 3) * 8 + 2 * tig;
            float e0 = __expf(acc[nt][0]);
            float e1 = __expf(acc[nt][1]);
            float e2 = __expf(acc[nt][2]);
            float e3 = __expf(acc[nt][3]);
            acc[nt][0] = e0; acc[nt][1] = e1; acc[nt][2] = e2; acc[nt][3] = e3;
            zz[2*rg]   += e0 + e1;
            zz[2*rg+1] += e2 + e3;
            if ((wmask[2*rg][q]   >> bit)       & 1u) aa[2*rg]   += e0;
            if ((wmask[2*rg][q]   >> (bit + 1)) & 1u) aa[2*rg]   += e1;
            if ((wmask[2*rg+1][q] >> bit)       & 1u) aa[2*rg+1] += e2;
            if ((wmask[2*rg+1][q] >> (bit + 1)) & 1u) aa[2*rg+1] += e3;
        }
    }
    #pragma unroll
    for (int o = 1; o <= 2; o <<= 1) {
        #pragma unroll
        for (int j = 0; j < 4; j++) {
            zz[j] += __shfl_xor_sync(0xffffffffu, zz[j], o);
            aa[j] += __shfl_xor_sync(0xffffffffu, aa[j], o);
        }
    }

    if (tig == 0) {
        #pragma unroll
        for (int j = 0; j < 4; j++) {
            red[ws * 32 + rows[j]]       = zz[j];
            red[256 + ws * 32 + rows[j]] = aa[j];
        }
    }
    __syncthreads();

    float inv[4];
    #pragma unroll
    for (int j = 0; j < 4; j++) {
        float zs = 0.f, as = 0.f;
        #pragma unroll
        for (int w = 0; w < 8; w++) {
            zs += red[w * 32 + rows[j]];
            as += red[256 + w * 32 + rows[j]];
        }
        inv[j] = 1.0f / (as + 1e-10f * (zs - as));
    }

    #pragma unroll
    for (int rg = 0; rg < 2; rg++) {
        float (*acc)[4] = rg ? acc1 : acc0;
        const int r0 = b * MAXLEN + utile + rows[2*rg];
        const int r1 = b * MAXLEN + utile + rows[2*rg+1];
        #pragma unroll
        for (int nt = 0; nt < 8; nt++) {
            const int q   = nt >> 2;
            const int bit = (nt & 3) * 8 + 2 * tig;
            const int sc  = ws * 64 + nt * 8 + 2 * tig;
            float2 v0, v1;
            v0.x = ((wmask[2*rg][q]   >> bit)       & 1u) ? acc[nt][0] * inv[2*rg]   : 0.f;
            v0.y = ((wmask[2*rg][q]   >> (bit + 1)) & 1u) ? acc[nt][1] * inv[2*rg]   : 0.f;
            v1.x = ((wmask[2*rg+1][q] >> bit)       & 1u) ? acc[nt][2] * inv[2*rg+1] : 0.f;
            v1.y = ((wmask[2*rg+1][q] >> (bit + 1)) & 1u) ? acc[nt][3] * inv[2*rg+1] : 0.f;
            *(float2*)&out[(size_t)r0 * SEQ + sc] = v0;
            *(float2*)&out[(size_t)r1 * SEQ + sc] = v1;
        }
    }
}

extern "C" void kernel_launch(void* const* d_in, const int* in_sizes, int n_in,
                              void* d_out, int out_size) {
    const float* M  = (const float*)d_in[0];
    const float* W  = (const float*)d_in[1];
    const int*   eb = (const int*)d_in[3];
    const int*   eu = (const int*)d_in[4];
    const int*   ev = (const int*)d_in[5];
    const int    E  = in_sizes[3];
    float* out = (float*)d_out;

    cudaFuncSetAttribute(mea_mma_kernel,
                         cudaFuncAttributeMaxDynamicSharedMemorySize, SM_TOTAL);

    const int edgeBlocks = (E + PREP_T - 1) / PREP_T;
    const int prepBlocks = edgeBlocks + CONVM_ITEMS / PREP_T
                         + (CONVW_ITEMS + PREP_T - 1) / PREP_T;
    prep_kernel<<<prepBlocks, PREP_T>>>(eb, eu, ev, E, edgeBlocks, M, W);
    mea_mma_kernel<<<dim3(MAXLEN / UTILE, BATCH), MMA_T, SM_TOTAL>>>(out);
}